// round 13
// baseline (speedup 1.0000x reference)
#include <cuda_runtime.h>
#include <cuda_fp16.h>
#include <cstdint>

#define FDIM 128
#define MAXN 50176   // 50000 rounded up to 128-row tiles
#define PAD  136     // smem row pitch in halves (272B, 16B-aligned, LDSM conflict-free)

// Scratch (allocation-free rule: __device__ globals)
__device__ __half g_Wsh[FDIM * FDIM];          // Ws = W + W^T, fp16
__device__ __half g_Gh[(size_t)MAXN * FDIM];   // G = X@Ws, fp16
__device__ __half g_Xh[(size_t)MAXN * FDIM];   // X copy, fp16
__device__ int    g_idx64;   // 1 if index arrays are int64, 0 if int32

// ---------------------------------------------------------------------------
// Kernel 0: detect index dtype (validated in R6: data is int32).
// ---------------------------------------------------------------------------
__global__ void detect_kernel(const void* __restrict__ mol, long long E) {
    const int* p = (const int*)mol;
    __shared__ int nonzero;
    if (threadIdx.x == 0) nonzero = 0;
    __syncthreads();
    long long half = E / 2;
    for (int s = threadIdx.x; s < 1024; s += blockDim.x) {
        long long e = (half * s) / 1024;
        if (p[2 * e + 1] != 0) atomicExch(&nonzero, 1);
    }
    __syncthreads();
    if (threadIdx.x == 0) g_idx64 = (nonzero == 0) ? 1 : 0;
}

// ---------------------------------------------------------------------------
// Kernel 1: Wsh = fp16(W + W^T)
// ---------------------------------------------------------------------------
__global__ void ws_kernel(const float* __restrict__ W) {
    int i = blockIdx.x;
    int j = threadIdx.x;
    g_Wsh[i * FDIM + j] = __float2half_rn(W[i * FDIM + j] + W[j * FDIM + i]);
}

// ---------------------------------------------------------------------------
// Kernel 1b: X -> fp16 copy (vectorized, ~5us)
// ---------------------------------------------------------------------------
__global__ void x2h_kernel(const float* __restrict__ X, long long nvec4) {
    long long t = (long long)blockIdx.x * blockDim.x + threadIdx.x;
    if (t < nvec4) {
        float4 v = ((const float4*)X)[t];
        __half2 h0 = __floats2half2_rn(v.x, v.y);
        __half2 h1 = __floats2half2_rn(v.z, v.w);
        uint2 o;
        o.x = *(unsigned*)&h0;
        o.y = *(unsigned*)&h1;
        ((uint2*)g_Xh)[t] = o;
    }
}

// ---------------------------------------------------------------------------
// Kernel 2: G = Xh @ Wsh via HMMA mma.sync.m16n8k16 (fp16 in, fp32 accum),
// fp16 epilogue. Block = 256 thr (8 warps), tile 128 rows x 128 cols.
// Dynamic smem: Xs[128][PAD] + Wss[128][PAD] halves (~70KB).
// ---------------------------------------------------------------------------
__device__ __forceinline__ void ldsm_x4(uint32_t addr, unsigned& r0, unsigned& r1,
                                        unsigned& r2, unsigned& r3) {
    asm volatile("ldmatrix.sync.aligned.m8n8.x4.shared.b16 {%0,%1,%2,%3}, [%4];"
                 : "=r"(r0), "=r"(r1), "=r"(r2), "=r"(r3) : "r"(addr));
}

__device__ __forceinline__ void ldsm_x4_t(uint32_t addr, unsigned& r0, unsigned& r1,
                                          unsigned& r2, unsigned& r3) {
    asm volatile("ldmatrix.sync.aligned.m8n8.x4.trans.shared.b16 {%0,%1,%2,%3}, [%4];"
                 : "=r"(r0), "=r"(r1), "=r"(r2), "=r"(r3) : "r"(addr));
}

__device__ __forceinline__ void mma16816(float* c, unsigned a0, unsigned a1,
                                         unsigned a2, unsigned a3,
                                         unsigned b0, unsigned b1) {
    asm volatile(
        "mma.sync.aligned.m16n8k16.row.col.f32.f16.f16.f32 "
        "{%0,%1,%2,%3}, {%4,%5,%6,%7}, {%8,%9}, {%0,%1,%2,%3};"
        : "+f"(c[0]), "+f"(c[1]), "+f"(c[2]), "+f"(c[3])
        : "r"(a0), "r"(a1), "r"(a2), "r"(a3), "r"(b0), "r"(b1));
}

__global__ __launch_bounds__(256) void gemm_kernel(int N) {
    extern __shared__ __align__(16) __half smem[];
    __half* Xs  = smem;                 // 128 x PAD
    __half* Wss = smem + 128 * PAD;     // 128 x PAD

    const int tid  = threadIdx.x;
    const int row0 = blockIdx.x * 128;

    // Load Ws tile (128 x 128 halves = 2048 uint4)
    for (int t = tid; t < 128 * 16; t += 256) {
        int r = t >> 4, c = t & 15;
        *(uint4*)&Wss[r * PAD + c * 8] = ((const uint4*)g_Wsh)[r * 16 + c];
    }
    // Load X tile (zero-fill past N)
    for (int t = tid; t < 128 * 16; t += 256) {
        int r = t >> 4, c = t & 15;
        int gr = row0 + r;
        uint4 v = (gr < N) ? ((const uint4*)g_Xh)[(size_t)gr * 16 + c]
                           : make_uint4(0u, 0u, 0u, 0u);
        *(uint4*)&Xs[r * PAD + c * 8] = v;
    }
    __syncthreads();

    const int warp = tid >> 5;
    const int lane = tid & 31;
    const int wrow = warp * 16;
    const int g    = lane >> 3;           // lane group 0..3

    // A ldmatrix lane address: g0: rows0-7,k+0 | g1: rows8-15,k+0 | g2: rows0-7,k+8 | g3: rows8-15,k+8
    const int aRow  = wrow + (lane & 7) + ((g & 1) ? 8 : 0);
    const int aKoff = (g >= 2) ? 8 : 0;
    // B (trans) lane address: g0: k0-7,n+0 | g1: k8-15,n+0 | g2: k0-7,n+8 | g3: k8-15,n+8
    const int bK    = (lane & 7) + ((g & 1) ? 8 : 0);
    const int bNoff = (g >= 2) ? 8 : 0;

    const uint32_t xsBase = (uint32_t)__cvta_generic_to_shared(Xs);
    const uint32_t wsBase = (uint32_t)__cvta_generic_to_shared(Wss);

    float c[16][4];
#pragma unroll
    for (int n = 0; n < 16; n++)
#pragma unroll
        for (int q = 0; q < 4; q++) c[n][q] = 0.f;

#pragma unroll
    for (int k0 = 0; k0 < 128; k0 += 16) {
        unsigned a0, a1, a2, a3;
        ldsm_x4(xsBase + (uint32_t)(aRow * PAD + k0 + aKoff) * 2, a0, a1, a2, a3);
#pragma unroll
        for (int nt = 0; nt < 16; nt += 2) {
            unsigned b0, b1, b2, b3;
            ldsm_x4_t(wsBase + (uint32_t)((bK + k0) * PAD + nt * 8 + bNoff) * 2,
                      b0, b1, b2, b3);
            mma16816(c[nt],     a0, a1, a2, a3, b0, b1);
            mma16816(c[nt + 1], a0, a1, a2, a3, b2, b3);
        }
    }

    // Epilogue: c0,c1 -> (row, col..col+1); c2,c3 -> (row+8, ...)
    const int erow = wrow + (lane >> 2);
    const int ecol4 = lane & 3;            // col pair index within n-tile
#pragma unroll
    for (int nt = 0; nt < 16; nt++) {
        int colh = nt * 4 + ecol4;         // half2 index within row (64 per row)
        int gr0 = row0 + erow;
        int gr1 = gr0 + 8;
        if (gr0 < N) {
            __half2 h = __floats2half2_rn(c[nt][0], c[nt][1]);
            ((unsigned*)g_Gh)[(size_t)gr0 * 64 + colh] = *(unsigned*)&h;
        }
        if (gr1 < N) {
            __half2 h = __floats2half2_rn(c[nt][2], c[nt][3]);
            ((unsigned*)g_Gh)[(size_t)gr1 * 64 + colh] = *(unsigned*)&h;
        }
    }
}

// ---------------------------------------------------------------------------
// Kernel 3: edge dot + segment sum, fp16 gathers (LDG.64/lane, 256B/row),
// 4 edges per warp per iteration, fp32 accumulation, smem segment bins.
// (unchanged from R11 passing version)
// ---------------------------------------------------------------------------
__device__ __forceinline__ float hdot4(uint2 ua, uint2 ub) {
    float2 a0 = __half22float2(*(const __half2*)&ua.x);
    float2 a1 = __half22float2(*(const __half2*)&ua.y);
    float2 b0 = __half22float2(*(const __half2*)&ub.x);
    float2 b1 = __half22float2(*(const __half2*)&ub.y);
    return fmaf(a0.x, b0.x, fmaf(a0.y, b0.y, fmaf(a1.x, b1.x, a1.y * b1.y)));
}

__global__ __launch_bounds__(256)
void edge_kernel(const void* __restrict__ nbr,
                 const void* __restrict__ mol,
                 long long E,
                 float* __restrict__ out,
                 int M) {
    extern __shared__ float acc[];
    for (int t = threadIdx.x; t < M; t += blockDim.x) acc[t] = 0.f;
    __syncthreads();

    const int lane = threadIdx.x & 31;
    const uint2* __restrict__ A = (const uint2*)g_Gh;   // row = 32 uint2
    const uint2* __restrict__ B = (const uint2*)g_Xh;
    const long long w  = ((long long)blockIdx.x * blockDim.x + threadIdx.x) >> 5;
    const long long nw = ((long long)gridDim.x * blockDim.x) >> 5;

    if (g_idx64 == 0) {
        const int* __restrict__ src = (const int*)nbr;
        const int* __restrict__ dst = src + E;
        const int* __restrict__ mm  = (const int*)mol;

        for (long long e0 = w * 4; e0 < E; e0 += nw * 4) {
            int i0, i1, i2, i3, j0, j1, j2, j3, m0, m1, m2, m3;
            float v1 = 1.f, v2 = 1.f, v3 = 1.f;
            if (e0 + 4 <= E) {
                int4 si = *(const int4*)(src + e0);
                int4 sj = *(const int4*)(dst + e0);
                int4 sm = *(const int4*)(mm + e0);
                i0 = si.x; i1 = si.y; i2 = si.z; i3 = si.w;
                j0 = sj.x; j1 = sj.y; j2 = sj.z; j3 = sj.w;
                m0 = sm.x; m1 = sm.y; m2 = sm.z; m3 = sm.w;
            } else {
                i0 = src[e0]; j0 = dst[e0]; m0 = mm[e0];
                i1 = i2 = i3 = 0; j1 = j2 = j3 = 0; m1 = m2 = m3 = 0;
                v1 = v2 = v3 = 0.f;
                if (e0 + 1 < E) { i1 = src[e0+1]; j1 = dst[e0+1]; m1 = mm[e0+1]; v1 = 1.f; }
                if (e0 + 2 < E) { i2 = src[e0+2]; j2 = dst[e0+2]; m2 = mm[e0+2]; v2 = 1.f; }
                if (e0 + 3 < E) { i3 = src[e0+3]; j3 = dst[e0+3]; m3 = mm[e0+3]; v3 = 1.f; }
            }

            uint2 a0 = A[(size_t)i0 * 32 + lane];
            uint2 b0 = B[(size_t)j0 * 32 + lane];
            uint2 a1 = A[(size_t)i1 * 32 + lane];
            uint2 b1 = B[(size_t)j1 * 32 + lane];
            uint2 a2 = A[(size_t)i2 * 32 + lane];
            uint2 b2 = B[(size_t)j2 * 32 + lane];
            uint2 a3 = A[(size_t)i3 * 32 + lane];
            uint2 b3 = B[(size_t)j3 * 32 + lane];

            float s0 = hdot4(a0, b0);
            float s1 = hdot4(a1, b1) * v1;
            float s2 = hdot4(a2, b2) * v2;
            float s3 = hdot4(a3, b3) * v3;

#pragma unroll
            for (int o = 16; o; o >>= 1) {
                s0 += __shfl_xor_sync(0xffffffffu, s0, o);
                s1 += __shfl_xor_sync(0xffffffffu, s1, o);
                s2 += __shfl_xor_sync(0xffffffffu, s2, o);
                s3 += __shfl_xor_sync(0xffffffffu, s3, o);
            }

            float sv = (lane == 0) ? s0 : (lane == 1) ? s1 : (lane == 2) ? s2 : s3;
            int   mv = (lane == 0) ? m0 : (lane == 1) ? m1 : (lane == 2) ? m2 : m3;
            if (lane < 4) atomicAdd(&acc[mv], sv);
        }
    } else {
        const long long* __restrict__ src = (const long long*)nbr;
        const long long* __restrict__ dst = src + E;
        const long long* __restrict__ mm  = (const long long*)mol;
        for (long long e = w; e < E; e += nw) {
            long long i = src[e];
            long long j = dst[e];
            uint2 a = A[(size_t)i * 32 + lane];
            uint2 b = B[(size_t)j * 32 + lane];
            float s = hdot4(a, b);
#pragma unroll
            for (int o = 16; o; o >>= 1) s += __shfl_xor_sync(0xffffffffu, s, o);
            if (lane == 0) atomicAdd(&acc[(int)mm[e]], s);
        }
    }

    __syncthreads();
    for (int t = threadIdx.x; t < M; t += blockDim.x)
        atomicAdd(&out[t], acc[t]);
}

// ---------------------------------------------------------------------------
// Launch
// ---------------------------------------------------------------------------
extern "C" void kernel_launch(void* const* d_in, const int* in_sizes, int n_in,
                              void* d_out, int out_size) {
    const float* X  = (const float*)d_in[0];   // [N, 128] fp32
    const float* W  = (const float*)d_in[1];   // [128, 128] fp32
    const void*  nbr = d_in[2];                // [2, E] int32 (detected) or int64
    const void*  mol = d_in[3];                // [E]
    float* out = (float*)d_out;                // [M] fp32

    const long long E = (long long)in_sizes[3];
    const int N = in_sizes[0] / FDIM;

    cudaMemsetAsync(d_out, 0, (size_t)out_size * sizeof(float), 0);

    detect_kernel<<<1, 256>>>(mol, E);

    ws_kernel<<<FDIM, FDIM>>>(W);

    long long nvec4 = (long long)N * FDIM / 4;
    x2h_kernel<<<(int)((nvec4 + 255) / 256), 256>>>(X, nvec4);

    // HMMA GEMM: dynamic smem = 2 tiles of 128 x PAD halves
    size_t gemm_smem = (size_t)2 * 128 * PAD * sizeof(__half);
    cudaFuncSetAttribute(gemm_kernel, cudaFuncAttributeMaxDynamicSharedMemorySize,
                         (int)gemm_smem);
    int gemm_blocks = (N + 127) / 128;
    gemm_kernel<<<gemm_blocks, 256, gemm_smem>>>(N);

    // 888 blocks, grid-stride 4-edge chunks.
    int eblocks = 888;
    size_t smem = (size_t)out_size * sizeof(float);
    edge_kernel<<<eblocks, 256, smem>>>(nbr, mol, E, out, out_size);
}

// round 14
// speedup vs baseline: 1.0619x; 1.0619x over previous
#include <cuda_runtime.h>
#include <cuda_fp16.h>
#include <cstdint>

#define FDIM 128
#define MAXN 50176   // 50000 rounded up to 128-row tiles
#define PAD  136     // smem row pitch in halves (272B, 16B-aligned, LDSM conflict-free)

// Scratch (allocation-free rule: __device__ globals)
__device__ __half g_Wsh[FDIM * FDIM];          // Ws = W + W^T, fp16
__device__ __half g_Gh[(size_t)MAXN * FDIM];   // G = X@Ws, fp16
__device__ __half g_Xh[(size_t)MAXN * FDIM];   // X copy, fp16
__device__ int    g_idx64;   // 1 if index arrays are int64, 0 if int32

// ---------------------------------------------------------------------------
// Kernel 0: detect index dtype (validated in R6: data is int32).
// ---------------------------------------------------------------------------
__global__ void detect_kernel(const void* __restrict__ mol, long long E) {
    const int* p = (const int*)mol;
    __shared__ int nonzero;
    if (threadIdx.x == 0) nonzero = 0;
    __syncthreads();
    long long half = E / 2;
    for (int s = threadIdx.x; s < 1024; s += blockDim.x) {
        long long e = (half * s) / 1024;
        if (p[2 * e + 1] != 0) atomicExch(&nonzero, 1);
    }
    __syncthreads();
    if (threadIdx.x == 0) g_idx64 = (nonzero == 0) ? 1 : 0;
}

// ---------------------------------------------------------------------------
// Kernel 1: Wsh = fp16(W + W^T)
// ---------------------------------------------------------------------------
__global__ void ws_kernel(const float* __restrict__ W) {
    int i = blockIdx.x;
    int j = threadIdx.x;
    g_Wsh[i * FDIM + j] = __float2half_rn(W[i * FDIM + j] + W[j * FDIM + i]);
}

// ---------------------------------------------------------------------------
// Kernel 1b: X -> fp16 copy (vectorized)
// ---------------------------------------------------------------------------
__global__ void x2h_kernel(const float* __restrict__ X, long long nvec4) {
    long long t = (long long)blockIdx.x * blockDim.x + threadIdx.x;
    if (t < nvec4) {
        float4 v = ((const float4*)X)[t];
        __half2 h0 = __floats2half2_rn(v.x, v.y);
        __half2 h1 = __floats2half2_rn(v.z, v.w);
        uint2 o;
        o.x = *(unsigned*)&h0;
        o.y = *(unsigned*)&h1;
        ((uint2*)g_Xh)[t] = o;
    }
}

// ---------------------------------------------------------------------------
// Kernel 2: G = Xh @ Wsh via HMMA mma.sync.m16n8k16 (fp16 in, fp32 accum).
// 18.8us measured — fine; edge kernel dominates.
// ---------------------------------------------------------------------------
__device__ __forceinline__ void ldsm_x4(uint32_t addr, unsigned& r0, unsigned& r1,
                                        unsigned& r2, unsigned& r3) {
    asm volatile("ldmatrix.sync.aligned.m8n8.x4.shared.b16 {%0,%1,%2,%3}, [%4];"
                 : "=r"(r0), "=r"(r1), "=r"(r2), "=r"(r3) : "r"(addr));
}

__device__ __forceinline__ void ldsm_x4_t(uint32_t addr, unsigned& r0, unsigned& r1,
                                          unsigned& r2, unsigned& r3) {
    asm volatile("ldmatrix.sync.aligned.m8n8.x4.trans.shared.b16 {%0,%1,%2,%3}, [%4];"
                 : "=r"(r0), "=r"(r1), "=r"(r2), "=r"(r3) : "r"(addr));
}

__device__ __forceinline__ void mma16816(float* c, unsigned a0, unsigned a1,
                                         unsigned a2, unsigned a3,
                                         unsigned b0, unsigned b1) {
    asm volatile(
        "mma.sync.aligned.m16n8k16.row.col.f32.f16.f16.f32 "
        "{%0,%1,%2,%3}, {%4,%5,%6,%7}, {%8,%9}, {%0,%1,%2,%3};"
        : "+f"(c[0]), "+f"(c[1]), "+f"(c[2]), "+f"(c[3])
        : "r"(a0), "r"(a1), "r"(a2), "r"(a3), "r"(b0), "r"(b1));
}

__global__ __launch_bounds__(256) void gemm_kernel(int N) {
    extern __shared__ __align__(16) __half smem[];
    __half* Xs  = smem;                 // 128 x PAD
    __half* Wss = smem + 128 * PAD;     // 128 x PAD

    const int tid  = threadIdx.x;
    const int row0 = blockIdx.x * 128;

    for (int t = tid; t < 128 * 16; t += 256) {
        int r = t >> 4, c = t & 15;
        *(uint4*)&Wss[r * PAD + c * 8] = ((const uint4*)g_Wsh)[r * 16 + c];
    }
    for (int t = tid; t < 128 * 16; t += 256) {
        int r = t >> 4, c = t & 15;
        int gr = row0 + r;
        uint4 v = (gr < N) ? ((const uint4*)g_Xh)[(size_t)gr * 16 + c]
                           : make_uint4(0u, 0u, 0u, 0u);
        *(uint4*)&Xs[r * PAD + c * 8] = v;
    }
    __syncthreads();

    const int warp = tid >> 5;
    const int lane = tid & 31;
    const int wrow = warp * 16;
    const int g    = lane >> 3;

    const int aRow  = wrow + (lane & 7) + ((g & 1) ? 8 : 0);
    const int aKoff = (g >= 2) ? 8 : 0;
    const int bK    = (lane & 7) + ((g & 1) ? 8 : 0);
    const int bNoff = (g >= 2) ? 8 : 0;

    const uint32_t xsBase = (uint32_t)__cvta_generic_to_shared(Xs);
    const uint32_t wsBase = (uint32_t)__cvta_generic_to_shared(Wss);

    float c[16][4];
#pragma unroll
    for (int n = 0; n < 16; n++)
#pragma unroll
        for (int q = 0; q < 4; q++) c[n][q] = 0.f;

#pragma unroll
    for (int k0 = 0; k0 < 128; k0 += 16) {
        unsigned a0, a1, a2, a3;
        ldsm_x4(xsBase + (uint32_t)(aRow * PAD + k0 + aKoff) * 2, a0, a1, a2, a3);
#pragma unroll
        for (int nt = 0; nt < 16; nt += 2) {
            unsigned b0, b1, b2, b3;
            ldsm_x4_t(wsBase + (uint32_t)((bK + k0) * PAD + nt * 8 + bNoff) * 2,
                      b0, b1, b2, b3);
            mma16816(c[nt],     a0, a1, a2, a3, b0, b1);
            mma16816(c[nt + 1], a0, a1, a2, a3, b2, b3);
        }
    }

    const int erow = wrow + (lane >> 2);
    const int ecol4 = lane & 3;
#pragma unroll
    for (int nt = 0; nt < 16; nt++) {
        int colh = nt * 4 + ecol4;
        int gr0 = row0 + erow;
        int gr1 = gr0 + 8;
        if (gr0 < N) {
            __half2 h = __floats2half2_rn(c[nt][0], c[nt][1]);
            ((unsigned*)g_Gh)[(size_t)gr0 * 64 + colh] = *(unsigned*)&h;
        }
        if (gr1 < N) {
            __half2 h = __floats2half2_rn(c[nt][2], c[nt][3]);
            ((unsigned*)g_Gh)[(size_t)gr1 * 64 + colh] = *(unsigned*)&h;
        }
    }
}

// ---------------------------------------------------------------------------
// Kernel 3: edge dot + segment sum. Half-warp per edge: 16 lanes x LDG.128
// cover one 256B fp16 row; one warp handles 8 edges/iter with 8 LDG.128
// (4KB) in flight. Butterfly reduce within 16-lane halves; atomics from
// lanes {0,16}. fp32 accumulation in smem segment bins.
// ---------------------------------------------------------------------------
__device__ __forceinline__ float hdot8(uint4 ua, uint4 ub) {
    float2 a0 = __half22float2(*(const __half2*)&ua.x);
    float2 a1 = __half22float2(*(const __half2*)&ua.y);
    float2 a2 = __half22float2(*(const __half2*)&ua.z);
    float2 a3 = __half22float2(*(const __half2*)&ua.w);
    float2 b0 = __half22float2(*(const __half2*)&ub.x);
    float2 b1 = __half22float2(*(const __half2*)&ub.y);
    float2 b2 = __half22float2(*(const __half2*)&ub.z);
    float2 b3 = __half22float2(*(const __half2*)&ub.w);
    float s = a0.x * b0.x;
    s = fmaf(a0.y, b0.y, s);
    s = fmaf(a1.x, b1.x, s);
    s = fmaf(a1.y, b1.y, s);
    s = fmaf(a2.x, b2.x, s);
    s = fmaf(a2.y, b2.y, s);
    s = fmaf(a3.x, b3.x, s);
    s = fmaf(a3.y, b3.y, s);
    return s;
}

__global__ __launch_bounds__(256)
void edge_kernel(const void* __restrict__ nbr,
                 const void* __restrict__ mol,
                 long long E,
                 float* __restrict__ out,
                 int M) {
    extern __shared__ float acc[];
    for (int t = threadIdx.x; t < M; t += blockDim.x) acc[t] = 0.f;
    __syncthreads();

    const int lane = threadIdx.x & 31;
    const int half = lane >> 4;          // 0: even edge of pair, 1: odd
    const int hl   = lane & 15;          // lane within half
    const uint4* __restrict__ A = (const uint4*)g_Gh;   // row = 16 uint4
    const uint4* __restrict__ B = (const uint4*)g_Xh;
    const long long w  = ((long long)blockIdx.x * blockDim.x + threadIdx.x) >> 5;
    const long long nw = ((long long)gridDim.x * blockDim.x) >> 5;

    if (g_idx64 == 0) {
        // ---- int32 path (the real data path) ----
        const int* __restrict__ src = (const int*)nbr;
        const int* __restrict__ dst = src + E;
        const int* __restrict__ mm  = (const int*)mol;

        for (long long e0 = w * 8; e0 < E; e0 += nw * 8) {
            int ii[8], jj[8], m8[8];
            float val[8];
            if (e0 + 8 <= E) {
                int4 s0 = *(const int4*)(src + e0);
                int4 s1 = *(const int4*)(src + e0 + 4);
                int4 d0 = *(const int4*)(dst + e0);
                int4 d1 = *(const int4*)(dst + e0 + 4);
                int4 q0 = *(const int4*)(mm + e0);
                int4 q1 = *(const int4*)(mm + e0 + 4);
                ii[0]=s0.x; ii[1]=s0.y; ii[2]=s0.z; ii[3]=s0.w;
                ii[4]=s1.x; ii[5]=s1.y; ii[6]=s1.z; ii[7]=s1.w;
                jj[0]=d0.x; jj[1]=d0.y; jj[2]=d0.z; jj[3]=d0.w;
                jj[4]=d1.x; jj[5]=d1.y; jj[6]=d1.z; jj[7]=d1.w;
                m8[0]=q0.x; m8[1]=q0.y; m8[2]=q0.z; m8[3]=q0.w;
                m8[4]=q1.x; m8[5]=q1.y; m8[6]=q1.z; m8[7]=q1.w;
#pragma unroll
                for (int q = 0; q < 8; q++) val[q] = 1.f;
            } else {
#pragma unroll
                for (int q = 0; q < 8; q++) {
                    if (e0 + q < E) {
                        ii[q] = src[e0+q]; jj[q] = dst[e0+q]; m8[q] = mm[e0+q];
                        val[q] = 1.f;
                    } else {
                        ii[q] = 0; jj[q] = 0; m8[q] = 0; val[q] = 0.f;
                    }
                }
            }

            // 8 LDG.128 in flight; each warp instruction serves 2 edges.
            uint4 av[4], bv[4];
#pragma unroll
            for (int p = 0; p < 4; p++) {
                int ie = half ? ii[2*p+1] : ii[2*p];
                int je = half ? jj[2*p+1] : jj[2*p];
                av[p] = A[(size_t)ie * 16 + hl];
                bv[p] = B[(size_t)je * 16 + hl];
            }

            float s[4];
#pragma unroll
            for (int p = 0; p < 4; p++)
                s[p] = hdot8(av[p], bv[p]) * (half ? val[2*p+1] : val[2*p]);

            // Butterfly within each 16-lane half (xor of bits 0..3)
#pragma unroll
            for (int p = 0; p < 4; p++) {
#pragma unroll
                for (int o = 8; o; o >>= 1)
                    s[p] += __shfl_xor_sync(0xffffffffu, s[p], o);
            }

            // lanes 0 and 16 commit each pair's two edges
#pragma unroll
            for (int p = 0; p < 4; p++) {
                int mv = half ? m8[2*p+1] : m8[2*p];
                if (hl == 0) atomicAdd(&acc[mv], s[p]);
            }
        }
    } else {
        // ---- int64 fallback (correctness only) ----
        const long long* __restrict__ src = (const long long*)nbr;
        const long long* __restrict__ dst = src + E;
        const long long* __restrict__ mm  = (const long long*)mol;
        const uint2* __restrict__ A2 = (const uint2*)g_Gh;
        const uint2* __restrict__ B2 = (const uint2*)g_Xh;
        for (long long e = w; e < E; e += nw) {
            long long i = src[e];
            long long j = dst[e];
            uint2 a = A2[(size_t)i * 32 + lane];
            uint2 b = B2[(size_t)j * 32 + lane];
            float2 a0 = __half22float2(*(const __half2*)&a.x);
            float2 a1 = __half22float2(*(const __half2*)&a.y);
            float2 b0 = __half22float2(*(const __half2*)&b.x);
            float2 b1 = __half22float2(*(const __half2*)&b.y);
            float s = fmaf(a0.x, b0.x, fmaf(a0.y, b0.y,
                      fmaf(a1.x, b1.x, a1.y * b1.y)));
#pragma unroll
            for (int o = 16; o; o >>= 1) s += __shfl_xor_sync(0xffffffffu, s, o);
            if (lane == 0) atomicAdd(&acc[(int)mm[e]], s);
        }
    }

    __syncthreads();
    for (int t = threadIdx.x; t < M; t += blockDim.x)
        atomicAdd(&out[t], acc[t]);
}

// ---------------------------------------------------------------------------
// Launch
// ---------------------------------------------------------------------------
extern "C" void kernel_launch(void* const* d_in, const int* in_sizes, int n_in,
                              void* d_out, int out_size) {
    const float* X  = (const float*)d_in[0];   // [N, 128] fp32
    const float* W  = (const float*)d_in[1];   // [128, 128] fp32
    const void*  nbr = d_in[2];                // [2, E] int32 (detected) or int64
    const void*  mol = d_in[3];                // [E]
    float* out = (float*)d_out;                // [M] fp32

    const long long E = (long long)in_sizes[3];
    const int N = in_sizes[0] / FDIM;

    cudaMemsetAsync(d_out, 0, (size_t)out_size * sizeof(float), 0);

    detect_kernel<<<1, 256>>>(mol, E);

    ws_kernel<<<FDIM, FDIM>>>(W);

    long long nvec4 = (long long)N * FDIM / 4;
    x2h_kernel<<<(int)((nvec4 + 255) / 256), 256>>>(X, nvec4);

    size_t gemm_smem = (size_t)2 * 128 * PAD * sizeof(__half);
    cudaFuncSetAttribute(gemm_kernel, cudaFuncAttributeMaxDynamicSharedMemorySize,
                         (int)gemm_smem);
    int gemm_blocks = (N + 127) / 128;
    gemm_kernel<<<gemm_blocks, 256, gemm_smem>>>(N);

    // 888 blocks x 256 threads, grid-stride over 8-edge chunks.
    int eblocks = 888;
    size_t smem = (size_t)out_size * sizeof(float);
    edge_kernel<<<eblocks, 256, smem>>>(nbr, mol, E, out, out_size);
}